// round 16
// baseline (speedup 1.0000x reference)
#include <cuda_runtime.h>
#include <math.h>

// One CTA per batch (B=4096), 128 threads: thread t = (row r = t>>1, half
// h = t&1) owning 32 elements of row r (cols [32h, 32h+32)) in registers.
// In the column phase thread t is (col c = t>>1, row-half h).
//
// Factored sinkhorn: x = diag(u) * E * diag(v), E = exp(a/(temp+1e-6)-gmax)
// fixed. Per iteration only the 64-vectors u, v are updated:
//   u_r *= 1/(u_r*(E v)_r + 1e-8);  v_c *= 1/(v_c*(E^T u)_c + 1e-8)
// Half-dots are reduced with one shfl_xor(1) (partners are adjacent lanes).
//
// smem layouts (all conflict-free for the access patterns used):
//  - E^T stored as per-thread 32-word chunks, stride 36 words (16B aligned):
//    LDS.128 banks = (4*lane + 4k) mod 32 -> all 32 banks per 8-lane phase.
//  - u, v stored with a 4-word gap between halves (word 32->36) so the two
//    broadcast reads (h=0 base 0, h=1 base 36) hit disjoint bank groups.
//
// Greedy unique argmax: iterated masked global argmax, tie-break = smallest
// flat index via monotone u64 key. Per-thread cached max over the FREE cols
// of its half (rescan only when the consumed column was the cached argmax).
// A half may be exhausted while its row is free -> emit key 0 (guarded).

#define NITER 30
#define CST 36     // E^T per-thread chunk stride (words)

__global__ __launch_bounds__(128, 7)
void sinkhorn_greedy_kernel(const float* __restrict__ cell_logits,
                            const float* __restrict__ pos_temp,
                            float* __restrict__ out)
{
    __shared__ float smT[128 * CST];                  // E^T chunks (18432 B)
    __shared__ __align__(16) float us[68];            // u with half-gap pad
    __shared__ __align__(16) float vs[68];            // v with half-gap pad
    __shared__ unsigned long long red[2][4];
    __shared__ int asn[64];

    const int b    = blockIdx.x;
    const int t    = threadIdx.x;        // 0..127
    const int r    = t >> 1;             // row (or column) index 0..63
    const int h    = t & 1;              // half 0/1
    const int warp = t >> 5;
    const int lane = t & 31;

    const float sc = 1.0f / (pos_temp[0] + 1e-6f);

    // ---- load my half-row (8 x LDG.128, fully coalesced), scale, max ----
    const float4* __restrict__ g4 =
        (const float4*)(cell_logits + (size_t)b * 4096 + (size_t)t * 32);

    float ex[32];
    float mx = -INFINITY;
#pragma unroll
    for (int k = 0; k < 8; k++) {
        float4 a = g4[k];
        ex[4*k+0] = a.x * sc;  ex[4*k+1] = a.y * sc;
        ex[4*k+2] = a.z * sc;  ex[4*k+3] = a.w * sc;
        mx = fmaxf(mx, fmaxf(fmaxf(ex[4*k+0], ex[4*k+1]),
                             fmaxf(ex[4*k+2], ex[4*k+3])));
    }
#pragma unroll
    for (int o = 16; o; o >>= 1)
        mx = fmaxf(mx, __shfl_xor_sync(0xffffffffu, mx, o));
    if (lane == 0) red[0][warp] = (unsigned long long)__float_as_uint(mx);
    __syncthreads();
    const float gmax = fmaxf(
        fmaxf(__uint_as_float((unsigned)red[0][0]),
              __uint_as_float((unsigned)red[0][1])),
        fmaxf(__uint_as_float((unsigned)red[0][2]),
              __uint_as_float((unsigned)red[0][3])));

    // ---- E = exp(scaled - gmax); scatter into E^T chunk layout ----
    // Column c's rows [32*hh, 32*hh+32) live at smT[(2c+hh)*CST + (r&31)].
    {
        const int rhi  = r >> 5;         // which row-half my row is in
        const int rlow = r & 31;
#pragma unroll
        for (int j = 0; j < 32; j++) {
            ex[j] = expf(ex[j] - gmax);
            const int c = 32*h + j;
            smT[(2*c + rhi)*CST + rlow] = ex[j];
        }
    }
    if (t < 64) {
        const int p = t + ((t >> 5) << 2);   // half-gap padded index
        us[p] = 1.0f;
        vs[p] = 1.0f;
    }
    __syncthreads();

    float u = 1.0f, vcol = 1.0f;
    const float4* __restrict__ vs4h = (const float4*)(vs + 36*h);
    const float4* __restrict__ us4h = (const float4*)(us + 36*h);
    const float4* __restrict__ myT  = (const float4*)(smT + t * CST);
    const int pad_idx = r + ((r >> 5) << 2);

    // ---- 30 sinkhorn iterations on scale vectors only ----
    for (int iter = 0; iter < NITER; iter++) {
        // row phase: thread (r,h) partial dot of E[r][32h..) with v
        float s = 0.0f;
#pragma unroll
        for (int k = 0; k < 8; k++) {
            float4 vv = vs4h[k];
            s += ex[4*k+0]*vv.x + ex[4*k+1]*vv.y
               + ex[4*k+2]*vv.z + ex[4*k+3]*vv.w;
        }
        s += __shfl_xor_sync(0xffffffffu, s, 1);     // partner half
        u *= 1.0f / (u * s + 1e-8f);
        if (h == 0) us[pad_idx] = u;
        __syncthreads();

        // col phase: thread (c=r, h) partial dot of E^T[c][32h..) with u
        s = 0.0f;
#pragma unroll
        for (int k = 0; k < 8; k++) {
            float4 ee = myT[k];
            float4 uu = us4h[k];
            s += ee.x*uu.x + ee.y*uu.y + ee.z*uu.z + ee.w*uu.w;
        }
        s += __shfl_xor_sync(0xffffffffu, s, 1);
        vcol *= 1.0f / (vcol * s + 1e-8f);
        if (h == 0) vs[pad_idx] = vcol;
        __syncthreads();
    }

    // ---- materialize my half-row of x = u * E * diag(v) ----
#pragma unroll
    for (int k = 0; k < 8; k++) {
        float4 vv = vs4h[k];
        ex[4*k+0] = u * ex[4*k+0] * vv.x;
        ex[4*k+1] = u * ex[4*k+1] * vv.y;
        ex[4*k+2] = u * ex[4*k+2] * vv.z;
        ex[4*k+3] = u * ex[4*k+3] * vv.w;
    }

    // ---- greedy unique argmax ----
    unsigned cm = 0u;            // used-col mask for MY half only
    bool rowfree = true;
    float best = -1.0f;
    int   bc   = 0;
#pragma unroll
    for (int j = 0; j < 32; j++)
        if (ex[j] > best) { best = ex[j]; bc = j; }

    for (int p = 0; p < 64; p++) {
        const int par = p & 1;
        unsigned long long key = 0ull;
        if (rowfree && best > -0.5f) {               // half may be exhausted
            unsigned flat = (unsigned)(r * 64 + 32*h + bc);
            key = ((unsigned long long)__float_as_uint(best) << 32)
                | (unsigned long long)(4095u - flat);
        }
#pragma unroll
        for (int o = 16; o; o >>= 1) {
            unsigned long long ok = __shfl_xor_sync(0xffffffffu, key, o);
            if (ok > key) key = ok;
        }
        if (lane == 0) red[par][warp] = key;
        __syncthreads();

        unsigned long long kw = red[par][0];
        unsigned long long k1 = red[par][1];  if (k1 > kw) kw = k1;
        unsigned long long k2 = red[par][2];  if (k2 > kw) kw = k2;
        unsigned long long k3 = red[par][3];  if (k3 > kw) kw = k3;

        const unsigned flat = 4095u - (unsigned)(kw & 0xffffffffull);
        const int wr = (int)(flat >> 6);
        const int wc = (int)(flat & 63u);

        if (r == wr) {
            rowfree = false;
            if (h == 0) asn[wr] = wc;
        }
        if ((wc >> 5) == h) {                        // consumed col in my half
            cm |= 1u << (wc & 31);
            if (rowfree && bc == (wc & 31)) {        // cached argmax consumed
                best = -1.0f; bc = 0;
#pragma unroll
                for (int j = 0; j < 32; j++)
                    if (!((cm >> j) & 1u) && ex[j] > best) { best = ex[j]; bc = j; }
            }
        }
        // no trailing barrier: next pick uses the other red[] buffer
    }
    __syncthreads();             // asn[] complete

    // ---- write hard permutation: my half-row, 8 x STG.128 ----
    const int a = asn[r] - 32*h;                     // local col or out-of-range
    float4* __restrict__ o4 = (float4*)(out + (size_t)b * 4096 + (size_t)t * 32);
#pragma unroll
    for (int k = 0; k < 8; k++) {
        float4 z;
        z.x = (a == 4*k+0) ? 1.0f : 0.0f;
        z.y = (a == 4*k+1) ? 1.0f : 0.0f;
        z.z = (a == 4*k+2) ? 1.0f : 0.0f;
        z.w = (a == 4*k+3) ? 1.0f : 0.0f;
        o4[k] = z;
    }
}

extern "C" void kernel_launch(void* const* d_in, const int* in_sizes, int n_in,
                              void* d_out, int out_size)
{
    const float* cell_logits = (const float*)d_in[0];
    const float* pos_temp    = (const float*)d_in[1];
    float* out               = (float*)d_out;

    const int B = in_sizes[0] / 4096;   // 4096 batches of 64x64
    sinkhorn_greedy_kernel<<<B, 128>>>(cell_logits, pos_temp, out);
}

// round 17
// speedup vs baseline: 1.2270x; 1.2270x over previous
#include <cuda_runtime.h>
#include <math.h>

// One CTA per batch (B=4096), 64 threads, thread t = row t (and column t in
// the column phase).
//
// Factored sinkhorn: x = diag(u) * E * diag(v) with E = exp(a/(temp+1e-6)
// - gmax) FIXED. Per iteration only the 64-vectors u, v change:
//   u_r *= 1/(u_r*(E v)_r + 1e-8);  v_c *= 1/(v_c*(E^T u)_c + 1e-8)
// E row lives in registers; E^T lives in smem (written once, read-only),
// stride 68 words so column reads are contiguous 16B-aligned conflict-free
// LDS.128. u/v are broadcast LDS.128.
//
// Dot products use 8 independent accumulators (chain depth 8 instead of 64)
// to kill the serial-FFMA latency chain that bound the previous version.
//
// Greedy unique argmax: iterated masked global argmax, tie-break smallest
// flat index via monotone u64 key; maintained per-row cached maxima, rescan
// only when the consumed column was the cached argmax. One barrier per pick
// (double-buffered reduction slots).

#define ST 68
#define NITER 30

__global__ __launch_bounds__(64)
void sinkhorn_greedy_kernel(const float* __restrict__ cell_logits,
                            const float* __restrict__ pos_temp,
                            float* __restrict__ out)
{
    __shared__ float smT[64 * ST];                    // E^T: smT[c*ST + r]
    __shared__ __align__(16) float us[64];
    __shared__ __align__(16) float vs[64];
    __shared__ unsigned long long red[2][2];
    __shared__ int asn[64];

    const int b    = blockIdx.x;
    const int t    = threadIdx.x;        // 0..63
    const int warp = t >> 5;
    const int lane = t & 31;

    const float sc = 1.0f / (pos_temp[0] + 1e-6f);

    // ---- load my row (16 x LDG.128, coalesced), scale, row max ----
    const float4* __restrict__ g4 =
        (const float4*)(cell_logits + (size_t)b * 4096 + (size_t)t * 64);

    float ex[64];
    float mx = -INFINITY;
#pragma unroll
    for (int k = 0; k < 16; k++) {
        float4 a = g4[k];
        ex[4*k+0] = a.x * sc;  ex[4*k+1] = a.y * sc;
        ex[4*k+2] = a.z * sc;  ex[4*k+3] = a.w * sc;
        mx = fmaxf(mx, fmaxf(fmaxf(ex[4*k+0], ex[4*k+1]),
                             fmaxf(ex[4*k+2], ex[4*k+3])));
    }
#pragma unroll
    for (int o = 16; o; o >>= 1)
        mx = fmaxf(mx, __shfl_xor_sync(0xffffffffu, mx, o));
    if (lane == 0) red[0][warp] = (unsigned long long)__float_as_uint(mx);
    __syncthreads();
    const float gmax = fmaxf(__uint_as_float((unsigned)red[0][0]),
                             __uint_as_float((unsigned)red[0][1]));

    // ---- E = exp(scaled - gmax); write E^T to smem; init scales ----
#pragma unroll
    for (int c = 0; c < 64; c++) {
        ex[c] = expf(ex[c] - gmax);
        smT[c * ST + t] = ex[c];          // conflict-free scalar STS
    }
    us[t] = 1.0f;
    vs[t] = 1.0f;
    __syncthreads();

    float u = 1.0f, vcol = 1.0f;
    const float4* __restrict__ vs4 = (const float4*)vs;
    const float4* __restrict__ us4 = (const float4*)us;
    const float4* __restrict__ myT = (const float4*)(smT + (size_t)t * ST);

    // ---- 30 sinkhorn iterations on the scale vectors only ----
    for (int iter = 0; iter < NITER; iter++) {
        // row phase: E row in regs, v broadcast from smem.
        // 8 independent FMA chains (depth 8), then tree combine.
        float p0 = 0.f, p1 = 0.f, p2 = 0.f, p3 = 0.f;
        float p4 = 0.f, p5 = 0.f, p6 = 0.f, p7 = 0.f;
#pragma unroll
        for (int k = 0; k < 16; k += 2) {
            float4 v0 = vs4[k];
            float4 v1 = vs4[k+1];
            p0 += ex[4*k+0]*v0.x;  p1 += ex[4*k+1]*v0.y;
            p2 += ex[4*k+2]*v0.z;  p3 += ex[4*k+3]*v0.w;
            p4 += ex[4*k+4]*v1.x;  p5 += ex[4*k+5]*v1.y;
            p6 += ex[4*k+6]*v1.z;  p7 += ex[4*k+7]*v1.w;
        }
        float s = ((p0 + p1) + (p2 + p3)) + ((p4 + p5) + (p6 + p7));
        u *= 1.0f / (u * s + 1e-8f);
        us[t] = u;
        __syncthreads();

        // col phase: E^T row contiguous LDS.128, u broadcast.
        p0 = p1 = p2 = p3 = p4 = p5 = p6 = p7 = 0.f;
#pragma unroll
        for (int k = 0; k < 16; k += 2) {
            float4 e0 = myT[k];
            float4 e1 = myT[k+1];
            float4 u0 = us4[k];
            float4 u1 = us4[k+1];
            p0 += e0.x*u0.x;  p1 += e0.y*u0.y;
            p2 += e0.z*u0.z;  p3 += e0.w*u0.w;
            p4 += e1.x*u1.x;  p5 += e1.y*u1.y;
            p6 += e1.z*u1.z;  p7 += e1.w*u1.w;
        }
        s = ((p0 + p1) + (p2 + p3)) + ((p4 + p5) + (p6 + p7));
        vcol *= 1.0f / (vcol * s + 1e-8f);
        vs[t] = vcol;
        __syncthreads();
    }

    // ---- materialize my row of x = u * E * diag(v) into registers ----
#pragma unroll
    for (int k = 0; k < 16; k++) {
        float4 vv = vs4[k];
        ex[4*k+0] = u * ex[4*k+0] * vv.x;
        ex[4*k+1] = u * ex[4*k+1] * vv.y;
        ex[4*k+2] = u * ex[4*k+2] * vv.z;
        ex[4*k+3] = u * ex[4*k+3] * vv.w;
    }

    // ---- greedy unique argmax (one barrier per pick) ----
    unsigned cm0 = 0u, cm1 = 0u;   // used-column bitmask (per thread)
    bool rowfree = true;
    float best = -1.0f;
    int   bc   = 0;
#pragma unroll
    for (int c = 0; c < 64; c++)
        if (ex[c] > best) { best = ex[c]; bc = c; }

    for (int p = 0; p < 64; p++) {
        const int par = p & 1;
        unsigned long long key = 0ull;
        if (rowfree) {
            unsigned flat = (unsigned)(t * 64 + bc);
            key = ((unsigned long long)__float_as_uint(best) << 32)
                | (unsigned long long)(4095u - flat);
        }
#pragma unroll
        for (int o = 16; o; o >>= 1) {
            unsigned long long ok = __shfl_xor_sync(0xffffffffu, key, o);
            if (ok > key) key = ok;
        }
        if (lane == 0) red[par][warp] = key;
        __syncthreads();

        unsigned long long k0 = red[par][0], k1 = red[par][1];
        unsigned long long kw = (k0 > k1) ? k0 : k1;
        const unsigned flat = 4095u - (unsigned)(kw & 0xffffffffull);
        const int wr = (int)(flat >> 6);
        const int wc = (int)(flat & 63u);

        if (t == wr) { rowfree = false; asn[wr] = wc; }
        if (wc < 32) cm0 |= (1u << wc);
        else         cm1 |= (1u << (wc - 32));

        if (rowfree && bc == wc) {       // cached argmax consumed -> rescan
            best = -1.0f; bc = 0;
#pragma unroll
            for (int c = 0; c < 64; c++) {
                bool used = (c < 32) ? (((cm0 >> c) & 1u) != 0u)
                                     : (((cm1 >> (c - 32)) & 1u) != 0u);
                if (!used && ex[c] > best) { best = ex[c]; bc = c; }
            }
        }
        // no trailing barrier: next pick writes the other red[] buffer
    }
    __syncthreads();                     // asn[] complete

    // ---- write hard permutation: my row, 16 x STG.128 ----
    const int a = asn[t];
    float4* __restrict__ o4 = (float4*)(out + (size_t)b * 4096 + (size_t)t * 64);
#pragma unroll
    for (int k = 0; k < 16; k++) {
        float4 z;
        z.x = (a == 4*k+0) ? 1.0f : 0.0f;
        z.y = (a == 4*k+1) ? 1.0f : 0.0f;
        z.z = (a == 4*k+2) ? 1.0f : 0.0f;
        z.w = (a == 4*k+3) ? 1.0f : 0.0f;
        o4[k] = z;
    }
}

extern "C" void kernel_launch(void* const* d_in, const int* in_sizes, int n_in,
                              void* d_out, int out_size)
{
    const float* cell_logits = (const float*)d_in[0];
    const float* pos_temp    = (const float*)d_in[1];
    float* out               = (float*)d_out;

    const int B = in_sizes[0] / 4096;   // 4096 batches of 64x64
    sinkhorn_greedy_kernel<<<B, 64>>>(cell_logits, pos_temp, out);
}